// round 14
// baseline (speedup 1.0000x reference)
#include <cuda_runtime.h>
#include <cuda_bf16.h>
#include <math.h>
#include <stdint.h>

#define T_TOK 8192
#define D_DIM 768
#define W_MAX 32
#define BANDW 64

// Scratch
__device__ float g_Qall[(size_t)T_TOK * D_DIM];            // 25 MB
__device__ float g_M [(size_t)T_TOK * BANDW];              // 2 MB (d half 0)
__device__ float g_M2[(size_t)T_TOK * BANDW];              // 2 MB (d half 1)
__device__ __nv_bfloat16 g_Ahi[(size_t)T_TOK * D_DIM];     // 12.6 MB
__device__ __nv_bfloat16 g_Alo[(size_t)T_TOK * D_DIM];
__device__ __nv_bfloat16 g_Bhi[(size_t)D_DIM * D_DIM];     // 1.18 MB
__device__ __nv_bfloat16 g_Blo[(size_t)D_DIM * D_DIM];

// ---------------- PTX helpers (sm_80-era only: safe at compute_103) --------
__device__ __forceinline__ uint32_t smem_u32(const void* p) {
    uint32_t a;
    asm("{ .reg .u64 t; cvta.to.shared.u64 t, %1; cvt.u32.u64 %0, t; }" : "=r"(a) : "l"(p));
    return a;
}
__device__ __forceinline__ void ldm_x4(uint32_t* r, uint32_t addr) {
    asm volatile("ldmatrix.sync.aligned.m8n8.x4.shared.b16 {%0,%1,%2,%3}, [%4];"
                 : "=r"(r[0]), "=r"(r[1]), "=r"(r[2]), "=r"(r[3]) : "r"(addr));
}
__device__ __forceinline__ void mma_bf16(float* d, const uint32_t* a, const uint32_t* b) {
    asm volatile("mma.sync.aligned.m16n8k16.row.col.f32.bf16.bf16.f32 "
                 "{%0,%1,%2,%3},{%4,%5,%6,%7},{%8,%9},{%0,%1,%2,%3};"
                 : "+f"(d[0]), "+f"(d[1]), "+f"(d[2]), "+f"(d[3])
                 : "r"(a[0]), "r"(a[1]), "r"(a[2]), "r"(a[3]), "r"(b[0]), "r"(b[1]));
}
#define CP_ASYNC16(dst, src) \
    asm volatile("cp.async.cg.shared.global [%0], [%1], 16;" :: "r"(dst), "l"(src))
#define CP_COMMIT() asm volatile("cp.async.commit_group;" ::: "memory")
#define CP_WAIT1()  asm volatile("cp.async.wait_group 1;" ::: "memory")
#define CP_WAIT0()  asm volatile("cp.async.wait_group 0;" ::: "memory")

// ---------------------------------------------------------------------------
// Kernel A: fp32 -> (hi, lo) bf16 split, vectorized by 4.
// ---------------------------------------------------------------------------
__global__ void cvt_kernel(const float* __restrict__ src,
                           __nv_bfloat16* __restrict__ hi,
                           __nv_bfloat16* __restrict__ lo, int n4)
{
    int i = blockIdx.x * blockDim.x + threadIdx.x;
    if (i >= n4) return;
    float4 v = reinterpret_cast<const float4*>(src)[i];
    float f[4] = {v.x, v.y, v.z, v.w};
    __nv_bfloat16 h[4], l[4];
    #pragma unroll
    for (int j = 0; j < 4; j++) {
        h[j] = __float2bfloat16_rn(f[j]);
        l[j] = __float2bfloat16_rn(f[j] - __bfloat162float(h[j]));
    }
    reinterpret_cast<__nv_bfloat162*>(hi)[2 * i]     = __nv_bfloat162(h[0], h[1]);
    reinterpret_cast<__nv_bfloat162*>(hi)[2 * i + 1] = __nv_bfloat162(h[2], h[3]);
    reinterpret_cast<__nv_bfloat162*>(lo)[2 * i]     = __nv_bfloat162(l[0], l[1]);
    reinterpret_cast<__nv_bfloat162*>(lo)[2 * i + 1] = __nv_bfloat162(l[2], l[3]);
}

// ---------------------------------------------------------------------------
// Kernel B: split-bf16 GEMM via mma.sync (HMMA).  Q_all = 3 bf16 products + bias.
// CTA: 128x128 tile, 8 warps (2x4), warp tile 64x32, BK=32, cp.async 2-stage.
// ---------------------------------------------------------------------------
#define SA 40                    // smem row stride in bf16 (80 B: conflict-free)
#define BUF_ELT (128 * SA)

__global__ __launch_bounds__(256, 2)
void qproj_mma_kernel(const float* __restrict__ bias)
{
    __shared__ __nv_bfloat16 Asb[2][BUF_ELT];
    __shared__ __nv_bfloat16 Bsb[2][BUF_ELT];

    const int tid  = threadIdx.x;
    const int lane = tid & 31;
    const int w    = tid >> 5;
    const int i0 = blockIdx.x * 128;          // token rows
    const int n0 = blockIdx.y * 128;          // output cols
    const int mw = (w >> 2) * 64;
    const int nw = (w & 3) * 32;

    const uint32_t aS0 = smem_u32(&Asb[0][0]);
    const uint32_t bS0 = smem_u32(&Bsb[0][0]);

    const int lrow0 = tid >> 2;
    const int lseg  = tid & 3;

    const __nv_bfloat16* const Abase[3] = {g_Ahi, g_Alo, g_Ahi};
    const __nv_bfloat16* const Bbase[3] = {g_Bhi, g_Bhi, g_Blo};

    float acc[4][4][4];
    #pragma unroll
    for (int mi = 0; mi < 4; mi++)
        #pragma unroll
        for (int ni = 0; ni < 4; ni++)
            #pragma unroll
            for (int r = 0; r < 4; r++) acc[mi][ni][r] = 0.f;

    float2 bia[4];
    #pragma unroll
    for (int ni = 0; ni < 4; ni++)
        bia[ni] = *reinterpret_cast<const float2*>(
            &bias[n0 + nw + ni * 8 + (lane & 3) * 2]);

    const int NCH = 72;   // 3 passes * 24 k-chunks

    {
        const __nv_bfloat16* Ap = Abase[0] + (size_t)(i0 + lrow0) * D_DIM;
        const __nv_bfloat16* Bp = Bbase[0] + (size_t)(n0 + lrow0) * D_DIM;
        const __nv_bfloat16* Ap2 = Abase[0] + (size_t)(i0 + lrow0 + 64) * D_DIM;
        const __nv_bfloat16* Bp2 = Bbase[0] + (size_t)(n0 + lrow0 + 64) * D_DIM;
        uint32_t da = aS0 + (lrow0 * SA + lseg * 8) * 2;
        uint32_t db = bS0 + (lrow0 * SA + lseg * 8) * 2;
        CP_ASYNC16(da, Ap + lseg * 8);
        CP_ASYNC16(db, Bp + lseg * 8);
        CP_ASYNC16(da + 64 * SA * 2, Ap2 + lseg * 8);
        CP_ASYNC16(db + 64 * SA * 2, Bp2 + lseg * 8);
        CP_COMMIT();
    }

    for (int c = 0; c < NCH; c++) {
        const int buf = c & 1;

        if (c + 1 < NCH) {
            const int p  = (c + 1) / 24;
            const int k0 = ((c + 1) % 24) * 32;
            const __nv_bfloat16* Ap = Abase[p] + (size_t)(i0 + lrow0) * D_DIM + k0 + lseg * 8;
            const __nv_bfloat16* Bp = Bbase[p] + (size_t)(n0 + lrow0) * D_DIM + k0 + lseg * 8;
            const __nv_bfloat16* Ap2 = Ap + (size_t)64 * D_DIM;
            const __nv_bfloat16* Bp2 = Bp + (size_t)64 * D_DIM;
            uint32_t da = aS0 + ((buf ^ 1) * BUF_ELT + lrow0 * SA + lseg * 8) * 2;
            uint32_t db = bS0 + ((buf ^ 1) * BUF_ELT + lrow0 * SA + lseg * 8) * 2;
            CP_ASYNC16(da, Ap);
            CP_ASYNC16(db, Bp);
            CP_ASYNC16(da + 64 * SA * 2, Ap2);
            CP_ASYNC16(db + 64 * SA * 2, Bp2);
            CP_COMMIT();
            CP_WAIT1();
        } else {
            CP_WAIT0();
        }
        __syncthreads();

        const uint32_t aS = aS0 + buf * BUF_ELT * 2;
        const uint32_t bS = bS0 + buf * BUF_ELT * 2;
        #pragma unroll
        for (int ks = 0; ks < 32; ks += 16) {
            uint32_t afr[4][4];
            #pragma unroll
            for (int mi = 0; mi < 4; mi++) {
                int r = mw + mi * 16 + (lane & 15);
                uint32_t ad = aS + (r * SA + ks + (lane >> 4) * 8) * 2;
                ldm_x4(afr[mi], ad);
            }
            uint32_t bfr[4][2];
            #pragma unroll
            for (int nt = 0; nt < 4; nt += 2) {
                int g = lane >> 3;
                int row = nw + (nt + (g >> 1)) * 8 + (lane & 7);
                uint32_t bd = bS + (row * SA + ks + (g & 1) * 8) * 2;
                uint32_t t[4];
                ldm_x4(t, bd);
                bfr[nt][0] = t[0]; bfr[nt][1] = t[1];
                bfr[nt + 1][0] = t[2]; bfr[nt + 1][1] = t[3];
            }
            #pragma unroll
            for (int mi = 0; mi < 4; mi++)
                #pragma unroll
                for (int ni = 0; ni < 4; ni++)
                    mma_bf16(acc[mi][ni], afr[mi], bfr[ni]);
        }
        __syncthreads();
    }

    #pragma unroll
    for (int mi = 0; mi < 4; mi++) {
        const int r0 = i0 + mw + mi * 16 + (lane >> 2);
        #pragma unroll
        for (int ni = 0; ni < 4; ni++) {
            const int gc = n0 + nw + ni * 8 + (lane & 3) * 2;
            float2 v0 = make_float2(acc[mi][ni][0] + bia[ni].x,
                                    acc[mi][ni][1] + bia[ni].y);
            float2 v1 = make_float2(acc[mi][ni][2] + bia[ni].x,
                                    acc[mi][ni][3] + bia[ni].y);
            *reinterpret_cast<float2*>(&g_Qall[(size_t)r0 * D_DIM + gc]) = v0;
            *reinterpret_cast<float2*>(&g_Qall[(size_t)(r0 + 8) * D_DIM + gc]) = v1;
        }
    }
}

// ---------------------------------------------------------------------------
// Kernel C: banded scores, D-split x2.
//   part y: Mp[y][i][o] = sum_{d in [384y,384y+384)} Qall[i][d] * emb[i+o-31][d]
// TI=32 tokens/block, 128 threads, per-thread 4x4 (i x o), 4 CTA/SM.
// grid = (256, 2) = 512 blocks -> ~one wave at 4 CTA/SM.
// ---------------------------------------------------------------------------
#define TI 32
#define KC 64
#define QS_W 36
#define ES_W 100
#define DHALF 384

__global__ __launch_bounds__(128, 4)
void band_kernel(const float* __restrict__ emb)
{
    __shared__ float Qs[KC][QS_W];    // 9.2 KB
    __shared__ float Es[KC][ES_W];    // 25.6 KB

    const int tid = threadIdx.x;
    const int tx = tid & 15;          // o-group (4 each)
    const int ty = tid >> 4;          // i-group (4 each), 0..7
    const int i0 = blockIdx.x * TI;
    const int dbase = blockIdx.y * DHALF;
    float* __restrict__ Mout = blockIdx.y ? g_M2 : g_M;

    float acc[4][4];
    #pragma unroll
    for (int i = 0; i < 4; i++)
        #pragma unroll
        for (int j = 0; j < 4; j++) acc[i][j] = 0.f;

    for (int d0 = dbase; d0 < dbase + DHALF; d0 += KC) {
        // Qall tile: 32 rows x 64 cols = 512 float4, 4/thread, transposed
        #pragma unroll
        for (int l = 0; l < 4; l++) {
            int idx = tid + l * 128;
            int row = idx >> 4;          // 0..31
            int c4  = idx & 15;
            float4 v = *reinterpret_cast<const float4*>(
                &g_Qall[(size_t)(i0 + row) * D_DIM + d0 + c4 * 4]);
            Qs[c4 * 4 + 0][row] = v.x;
            Qs[c4 * 4 + 1][row] = v.y;
            Qs[c4 * 4 + 2][row] = v.z;
            Qs[c4 * 4 + 3][row] = v.w;
        }
        // emb tile: 96 rows x 64 cols = 1536 float4, 12/thread
        #pragma unroll
        for (int l = 0; l < 12; l++) {
            int idx = tid + l * 128;
            int row = idx >> 4;          // 0..95
            int c4  = idx & 15;
            int r = i0 - 31 + row;
            r = min(max(r, 0), T_TOK - 1);   // clamped rows never consumed
            float4 v = *reinterpret_cast<const float4*>(
                &emb[(size_t)r * D_DIM + d0 + c4 * 4]);
            Es[c4 * 4 + 0][row] = v.x;
            Es[c4 * 4 + 1][row] = v.y;
            Es[c4 * 4 + 2][row] = v.z;
            Es[c4 * 4 + 3][row] = v.w;
        }
        __syncthreads();

        const int ebase = ty * 4 + tx * 4;
        #pragma unroll
        for (int kk = 0; kk < KC; kk++) {
            float4 av = *reinterpret_cast<const float4*>(&Qs[kk][ty * 4]);
            float4 e0 = *reinterpret_cast<const float4*>(&Es[kk][ebase]);
            float4 e1 = *reinterpret_cast<const float4*>(&Es[kk][ebase + 4]);
            float a[4] = {av.x, av.y, av.z, av.w};
            float e[8] = {e0.x, e0.y, e0.z, e0.w, e1.x, e1.y, e1.z, e1.w};
            #pragma unroll
            for (int i = 0; i < 4; i++)
                #pragma unroll
                for (int j = 0; j < 4; j++)
                    acc[i][j] = fmaf(a[i], e[i + j], acc[i][j]);
        }
        __syncthreads();
    }

    #pragma unroll
    for (int i = 0; i < 4; i++) {
        float4 v = make_float4(acc[i][0], acc[i][1], acc[i][2], acc[i][3]);
        *reinterpret_cast<float4*>(
            &Mout[(size_t)(i0 + ty * 4 + i) * BANDW + tx * 4]) = v;
    }
}

// ---------------------------------------------------------------------------
// Kernel D: 2 warps per span. Both warps compute csum (cheap, band in L2);
// each writes half of the 768-d epilogue.
// ---------------------------------------------------------------------------
__global__ __launch_bounds__(256)
void span_out_kernel(const float* __restrict__ emb,
                     const int*   __restrict__ spans,
                     float*       __restrict__ out,
                     int n)
{
    const int gw   = (blockIdx.x * blockDim.x + threadIdx.x) >> 5;
    const int lane = threadIdx.x & 31;
    const int span = gw >> 1;
    const int half = gw & 1;
    if (span >= n) return;

    const int start = spans[2 * span];
    const int L     = spans[2 * span + 1] - start + 1;

    float csum = 0.f;
    for (int q = 0; q < L; q++) {
        const size_t off = (size_t)(start + q) * BANDW + (lane - q + 31);
        float s = (lane < L) ? (g_M[off] + g_M2[off]) : -INFINITY;
        float m = s;
        #pragma unroll
        for (int o = 16; o > 0; o >>= 1) m = fmaxf(m, __shfl_xor_sync(0xffffffffu, m, o));
        float e = (lane < L) ? __expf(s - m) : 0.f;
        float sum = e;
        #pragma unroll
        for (int o = 16; o > 0; o >>= 1) sum += __shfl_xor_sync(0xffffffffu, sum, o);
        csum += e / sum;
    }

    // Epilogue: this warp handles d in [half*64 .. ) stepping 128 (two 32-chunks)
    const float* eb = emb + (size_t)start * D_DIM;
    float* od = out + (size_t)span * D_DIM;
    for (int db = half * 64; db < D_DIM; db += 128) {
        float acc0 = 0.f, acc1 = 0.f;
        for (int k = 0; k < L; k++) {
            float c = __shfl_sync(0xffffffffu, csum, k);
            const float* er = eb + (size_t)k * D_DIM + db;
            acc0 = fmaf(c, er[lane], acc0);
            acc1 = fmaf(c, er[lane + 32], acc1);
        }
        od[db + lane]      = acc0;
        od[db + lane + 32] = acc1;
    }
}

// ---------------------------------------------------------------------------
extern "C" void kernel_launch(void* const* d_in, const int* in_sizes, int n_in,
                              void* d_out, int out_size)
{
    const float* emb   = (const float*)d_in[0];
    const int*   spans = (const int*)  d_in[1];
    const float* Wq    = (const float*)d_in[2];
    const float* bq    = (const float*)d_in[3];
    float* out = (float*)d_out;

    const int n_spans = in_sizes[1] / 2;

    __nv_bfloat16 *ahi, *alo, *bhi, *blo;
    cudaGetSymbolAddress((void**)&ahi, g_Ahi);
    cudaGetSymbolAddress((void**)&alo, g_Alo);
    cudaGetSymbolAddress((void**)&bhi, g_Bhi);
    cudaGetSymbolAddress((void**)&blo, g_Blo);

    const int nA4 = T_TOK * D_DIM / 4;
    const int nB4 = D_DIM * D_DIM / 4;
    cvt_kernel<<<(nA4 + 255) / 256, 256>>>(emb, ahi, alo, nA4);
    cvt_kernel<<<(nB4 + 255) / 256, 256>>>(Wq, bhi, blo, nB4);

    dim3 gq(T_TOK / 128, D_DIM / 128);
    qproj_mma_kernel<<<gq, 256>>>(bq);

    dim3 gb(T_TOK / TI, 2);
    band_kernel<<<gb, 128>>>(emb);

    const int blocks = (n_spans * 64 + 255) / 256;
    span_out_kernel<<<blocks, 256>>>(emb, spans, out, n_spans);
}

// round 15
// speedup vs baseline: 1.1146x; 1.1146x over previous
#include <cuda_runtime.h>
#include <cuda_bf16.h>
#include <math.h>
#include <stdint.h>

#define T_TOK 8192
#define D_DIM 768
#define W_MAX 32
#define BANDW 64

// Scratch
__device__ float g_Qall[(size_t)T_TOK * D_DIM];            // 25 MB
__device__ float g_M[(size_t)T_TOK * BANDW];               // 2 MB banded scores
__device__ __nv_bfloat16 g_Ahi[(size_t)T_TOK * D_DIM];     // 12.6 MB
__device__ __nv_bfloat16 g_Alo[(size_t)T_TOK * D_DIM];
__device__ __nv_bfloat16 g_Bhi[(size_t)D_DIM * D_DIM];     // 1.18 MB
__device__ __nv_bfloat16 g_Blo[(size_t)D_DIM * D_DIM];

// ---------------- PTX helpers (sm_80-era only: safe at compute_103) --------
__device__ __forceinline__ uint32_t smem_u32(const void* p) {
    uint32_t a;
    asm("{ .reg .u64 t; cvta.to.shared.u64 t, %1; cvt.u32.u64 %0, t; }" : "=r"(a) : "l"(p));
    return a;
}
__device__ __forceinline__ void ldm_x4(uint32_t* r, uint32_t addr) {
    asm volatile("ldmatrix.sync.aligned.m8n8.x4.shared.b16 {%0,%1,%2,%3}, [%4];"
                 : "=r"(r[0]), "=r"(r[1]), "=r"(r[2]), "=r"(r[3]) : "r"(addr));
}
__device__ __forceinline__ void mma_bf16(float* d, const uint32_t* a, const uint32_t* b) {
    asm volatile("mma.sync.aligned.m16n8k16.row.col.f32.bf16.bf16.f32 "
                 "{%0,%1,%2,%3},{%4,%5,%6,%7},{%8,%9},{%0,%1,%2,%3};"
                 : "+f"(d[0]), "+f"(d[1]), "+f"(d[2]), "+f"(d[3])
                 : "r"(a[0]), "r"(a[1]), "r"(a[2]), "r"(a[3]), "r"(b[0]), "r"(b[1]));
}
#define CP_ASYNC16(dst, src) \
    asm volatile("cp.async.cg.shared.global [%0], [%1], 16;" :: "r"(dst), "l"(src))
#define CP_COMMIT() asm volatile("cp.async.commit_group;" ::: "memory")
#define CP_WAIT1()  asm volatile("cp.async.wait_group 1;" ::: "memory")
#define CP_WAIT0()  asm volatile("cp.async.wait_group 0;" ::: "memory")

// ---------------------------------------------------------------------------
// Kernel A: fp32 -> (hi, lo) bf16 split, vectorized by 4.
// ---------------------------------------------------------------------------
__global__ void cvt_kernel(const float* __restrict__ src,
                           __nv_bfloat16* __restrict__ hi,
                           __nv_bfloat16* __restrict__ lo, int n4)
{
    int i = blockIdx.x * blockDim.x + threadIdx.x;
    if (i >= n4) return;
    float4 v = reinterpret_cast<const float4*>(src)[i];
    float f[4] = {v.x, v.y, v.z, v.w};
    __nv_bfloat16 h[4], l[4];
    #pragma unroll
    for (int j = 0; j < 4; j++) {
        h[j] = __float2bfloat16_rn(f[j]);
        l[j] = __float2bfloat16_rn(f[j] - __bfloat162float(h[j]));
    }
    reinterpret_cast<__nv_bfloat162*>(hi)[2 * i]     = __nv_bfloat162(h[0], h[1]);
    reinterpret_cast<__nv_bfloat162*>(hi)[2 * i + 1] = __nv_bfloat162(h[2], h[3]);
    reinterpret_cast<__nv_bfloat162*>(lo)[2 * i]     = __nv_bfloat162(l[0], l[1]);
    reinterpret_cast<__nv_bfloat162*>(lo)[2 * i + 1] = __nv_bfloat162(l[2], l[3]);
}

// ---------------------------------------------------------------------------
// Kernel B: split-bf16 GEMM via mma.sync (HMMA).  Q_all = 3 bf16 products + bias.
// CTA: 128x128 tile, 8 warps (2x4), warp tile 64x32, BK=32, cp.async 2-stage.
// ---------------------------------------------------------------------------
#define SA 40                    // smem row stride in bf16 (80 B: conflict-free)
#define BUF_ELT (128 * SA)

__global__ __launch_bounds__(256, 2)
void qproj_mma_kernel(const float* __restrict__ bias)
{
    __shared__ __nv_bfloat16 Asb[2][BUF_ELT];
    __shared__ __nv_bfloat16 Bsb[2][BUF_ELT];

    const int tid  = threadIdx.x;
    const int lane = tid & 31;
    const int w    = tid >> 5;
    const int i0 = blockIdx.x * 128;          // token rows
    const int n0 = blockIdx.y * 128;          // output cols
    const int mw = (w >> 2) * 64;
    const int nw = (w & 3) * 32;

    const uint32_t aS0 = smem_u32(&Asb[0][0]);
    const uint32_t bS0 = smem_u32(&Bsb[0][0]);

    const int lrow0 = tid >> 2;
    const int lseg  = tid & 3;

    const __nv_bfloat16* const Abase[3] = {g_Ahi, g_Alo, g_Ahi};
    const __nv_bfloat16* const Bbase[3] = {g_Bhi, g_Bhi, g_Blo};

    float acc[4][4][4];
    #pragma unroll
    for (int mi = 0; mi < 4; mi++)
        #pragma unroll
        for (int ni = 0; ni < 4; ni++)
            #pragma unroll
            for (int r = 0; r < 4; r++) acc[mi][ni][r] = 0.f;

    float2 bia[4];
    #pragma unroll
    for (int ni = 0; ni < 4; ni++)
        bia[ni] = *reinterpret_cast<const float2*>(
            &bias[n0 + nw + ni * 8 + (lane & 3) * 2]);

    const int NCH = 72;   // 3 passes * 24 k-chunks

    {
        const __nv_bfloat16* Ap = Abase[0] + (size_t)(i0 + lrow0) * D_DIM;
        const __nv_bfloat16* Bp = Bbase[0] + (size_t)(n0 + lrow0) * D_DIM;
        const __nv_bfloat16* Ap2 = Abase[0] + (size_t)(i0 + lrow0 + 64) * D_DIM;
        const __nv_bfloat16* Bp2 = Bbase[0] + (size_t)(n0 + lrow0 + 64) * D_DIM;
        uint32_t da = aS0 + (lrow0 * SA + lseg * 8) * 2;
        uint32_t db = bS0 + (lrow0 * SA + lseg * 8) * 2;
        CP_ASYNC16(da, Ap + lseg * 8);
        CP_ASYNC16(db, Bp + lseg * 8);
        CP_ASYNC16(da + 64 * SA * 2, Ap2 + lseg * 8);
        CP_ASYNC16(db + 64 * SA * 2, Bp2 + lseg * 8);
        CP_COMMIT();
    }

    for (int c = 0; c < NCH; c++) {
        const int buf = c & 1;

        if (c + 1 < NCH) {
            const int p  = (c + 1) / 24;
            const int k0 = ((c + 1) % 24) * 32;
            const __nv_bfloat16* Ap = Abase[p] + (size_t)(i0 + lrow0) * D_DIM + k0 + lseg * 8;
            const __nv_bfloat16* Bp = Bbase[p] + (size_t)(n0 + lrow0) * D_DIM + k0 + lseg * 8;
            const __nv_bfloat16* Ap2 = Ap + (size_t)64 * D_DIM;
            const __nv_bfloat16* Bp2 = Bp + (size_t)64 * D_DIM;
            uint32_t da = aS0 + ((buf ^ 1) * BUF_ELT + lrow0 * SA + lseg * 8) * 2;
            uint32_t db = bS0 + ((buf ^ 1) * BUF_ELT + lrow0 * SA + lseg * 8) * 2;
            CP_ASYNC16(da, Ap);
            CP_ASYNC16(db, Bp);
            CP_ASYNC16(da + 64 * SA * 2, Ap2);
            CP_ASYNC16(db + 64 * SA * 2, Bp2);
            CP_COMMIT();
            CP_WAIT1();
        } else {
            CP_WAIT0();
        }
        __syncthreads();

        const uint32_t aS = aS0 + buf * BUF_ELT * 2;
        const uint32_t bS = bS0 + buf * BUF_ELT * 2;
        #pragma unroll
        for (int ks = 0; ks < 32; ks += 16) {
            uint32_t afr[4][4];
            #pragma unroll
            for (int mi = 0; mi < 4; mi++) {
                int r = mw + mi * 16 + (lane & 15);
                uint32_t ad = aS + (r * SA + ks + (lane >> 4) * 8) * 2;
                ldm_x4(afr[mi], ad);
            }
            uint32_t bfr[4][2];
            #pragma unroll
            for (int nt = 0; nt < 4; nt += 2) {
                int g = lane >> 3;
                int row = nw + (nt + (g >> 1)) * 8 + (lane & 7);
                uint32_t bd = bS + (row * SA + ks + (g & 1) * 8) * 2;
                uint32_t t[4];
                ldm_x4(t, bd);
                bfr[nt][0] = t[0]; bfr[nt][1] = t[1];
                bfr[nt + 1][0] = t[2]; bfr[nt + 1][1] = t[3];
            }
            #pragma unroll
            for (int mi = 0; mi < 4; mi++)
                #pragma unroll
                for (int ni = 0; ni < 4; ni++)
                    mma_bf16(acc[mi][ni], afr[mi], bfr[ni]);
        }
        __syncthreads();
    }

    #pragma unroll
    for (int mi = 0; mi < 4; mi++) {
        const int r0 = i0 + mw + mi * 16 + (lane >> 2);
        #pragma unroll
        for (int ni = 0; ni < 4; ni++) {
            const int gc = n0 + nw + ni * 8 + (lane & 3) * 2;
            float2 v0 = make_float2(acc[mi][ni][0] + bia[ni].x,
                                    acc[mi][ni][1] + bia[ni].y);
            float2 v1 = make_float2(acc[mi][ni][2] + bia[ni].x,
                                    acc[mi][ni][3] + bia[ni].y);
            *reinterpret_cast<float2*>(&g_Qall[(size_t)r0 * D_DIM + gc]) = v0;
            *reinterpret_cast<float2*>(&g_Qall[(size_t)(r0 + 8) * D_DIM + gc]) = v1;
        }
    }
}

// ---------------------------------------------------------------------------
// Kernel C: banded scores M[i][o] = Qall[i] . emb[i + o - 31]  (R13 config)
// TI=64 tokens/block (grid 128), 256 threads, 4x4 per thread, KC=64.
// ---------------------------------------------------------------------------
#define TI 64
#define KC 64
#define QS_W 68
#define ES_W 132

__global__ __launch_bounds__(256)
void band_kernel(const float* __restrict__ emb)
{
    __shared__ float Qs[KC][QS_W];
    __shared__ float Es[KC][ES_W];

    const int tid = threadIdx.x;
    const int tx = tid & 15;
    const int ty = tid >> 4;
    const int i0 = blockIdx.x * TI;

    float acc[4][4];
    #pragma unroll
    for (int i = 0; i < 4; i++)
        #pragma unroll
        for (int j = 0; j < 4; j++) acc[i][j] = 0.f;

    for (int d0 = 0; d0 < D_DIM; d0 += KC) {
        #pragma unroll
        for (int l = 0; l < 4; l++) {
            int idx = tid + l * 256;
            int row = idx >> 4;
            int c4  = idx & 15;
            float4 v = *reinterpret_cast<const float4*>(
                &g_Qall[(size_t)(i0 + row) * D_DIM + d0 + c4 * 4]);
            Qs[c4 * 4 + 0][row] = v.x;
            Qs[c4 * 4 + 1][row] = v.y;
            Qs[c4 * 4 + 2][row] = v.z;
            Qs[c4 * 4 + 3][row] = v.w;
        }
        #pragma unroll
        for (int l = 0; l < 8; l++) {
            int idx = tid + l * 256;
            int row = idx >> 4;
            int c4  = idx & 15;
            int r = i0 - 31 + row;
            r = min(max(r, 0), T_TOK - 1);
            float4 v = *reinterpret_cast<const float4*>(
                &emb[(size_t)r * D_DIM + d0 + c4 * 4]);
            Es[c4 * 4 + 0][row] = v.x;
            Es[c4 * 4 + 1][row] = v.y;
            Es[c4 * 4 + 2][row] = v.z;
            Es[c4 * 4 + 3][row] = v.w;
        }
        __syncthreads();

        const int ebase = ty * 4 + tx * 4;
        #pragma unroll
        for (int kk = 0; kk < KC; kk++) {
            float4 av = *reinterpret_cast<const float4*>(&Qs[kk][ty * 4]);
            float4 e0 = *reinterpret_cast<const float4*>(&Es[kk][ebase]);
            float4 e1 = *reinterpret_cast<const float4*>(&Es[kk][ebase + 4]);
            float a[4] = {av.x, av.y, av.z, av.w};
            float e[8] = {e0.x, e0.y, e0.z, e0.w, e1.x, e1.y, e1.z, e1.w};
            #pragma unroll
            for (int i = 0; i < 4; i++)
                #pragma unroll
                for (int j = 0; j < 4; j++)
                    acc[i][j] = fmaf(a[i], e[i + j], acc[i][j]);
        }
        __syncthreads();
    }

    #pragma unroll
    for (int i = 0; i < 4; i++) {
        float4 v = make_float4(acc[i][0], acc[i][1], acc[i][2], acc[i][3]);
        *reinterpret_cast<float4*>(
            &g_M[(size_t)(i0 + ty * 4 + i) * BANDW + tx * 4]) = v;
    }
}

// ---------------------------------------------------------------------------
// Kernel D: one warp per span. Softmax column-sums from the band, then a
// SINGLE k-pass epilogue with 24 fp32 accumulators (6 x float4 per lane):
// per k = 1 shfl + 6 independent LDG.128 + 24 FMA  -> L2-BW bound.
// ---------------------------------------------------------------------------
__global__ __launch_bounds__(256)
void span_out_kernel(const float* __restrict__ emb,
                     const int*   __restrict__ spans,
                     float*       __restrict__ out,
                     int n)
{
    const int warp = (blockIdx.x * blockDim.x + threadIdx.x) >> 5;
    const int lane = threadIdx.x & 31;
    if (warp >= n) return;

    const int start = spans[2 * warp];
    const int L     = spans[2 * warp + 1] - start + 1;

    // --- softmax column sums (lane k holds csum[k]) ---
    float csum = 0.f;
    for (int q = 0; q < L; q++) {
        float s = (lane < L)
            ? g_M[(size_t)(start + q) * BANDW + (lane - q + 31)]
            : -INFINITY;
        float m = s;
        #pragma unroll
        for (int o = 16; o > 0; o >>= 1) m = fmaxf(m, __shfl_xor_sync(0xffffffffu, m, o));
        float e = (lane < L) ? __expf(s - m) : 0.f;
        float sum = e;
        #pragma unroll
        for (int o = 16; o > 0; o >>= 1) sum += __shfl_xor_sync(0xffffffffu, sum, o);
        csum += e / sum;
    }

    // --- epilogue: out = csum @ E, one pass over k, 24 accumulators ---
    const float4* eb4 = reinterpret_cast<const float4*>(emb + (size_t)start * D_DIM);
    float4 a[6];
    #pragma unroll
    for (int j = 0; j < 6; j++) a[j] = make_float4(0.f, 0.f, 0.f, 0.f);

    #pragma unroll 2
    for (int k = 0; k < L; k++) {
        float c = __shfl_sync(0xffffffffu, csum, k);
        const float4* er = eb4 + (size_t)k * (D_DIM / 4) + lane;
        #pragma unroll
        for (int j = 0; j < 6; j++) {
            float4 e = er[j * 32];
            a[j].x = fmaf(c, e.x, a[j].x);
            a[j].y = fmaf(c, e.y, a[j].y);
            a[j].z = fmaf(c, e.z, a[j].z);
            a[j].w = fmaf(c, e.w, a[j].w);
        }
    }

    float4* od4 = reinterpret_cast<float4*>(out + (size_t)warp * D_DIM) + lane;
    #pragma unroll
    for (int j = 0; j < 6; j++) od4[j * 32] = a[j];
}

// ---------------------------------------------------------------------------
extern "C" void kernel_launch(void* const* d_in, const int* in_sizes, int n_in,
                              void* d_out, int out_size)
{
    const float* emb   = (const float*)d_in[0];
    const int*   spans = (const int*)  d_in[1];
    const float* Wq    = (const float*)d_in[2];
    const float* bq    = (const float*)d_in[3];
    float* out = (float*)d_out;

    const int n_spans = in_sizes[1] / 2;

    __nv_bfloat16 *ahi, *alo, *bhi, *blo;
    cudaGetSymbolAddress((void**)&ahi, g_Ahi);
    cudaGetSymbolAddress((void**)&alo, g_Alo);
    cudaGetSymbolAddress((void**)&bhi, g_Bhi);
    cudaGetSymbolAddress((void**)&blo, g_Blo);

    const int nA4 = T_TOK * D_DIM / 4;
    const int nB4 = D_DIM * D_DIM / 4;
    cvt_kernel<<<(nA4 + 255) / 256, 256>>>(emb, ahi, alo, nA4);
    cvt_kernel<<<(nB4 + 255) / 256, 256>>>(Wq, bhi, blo, nB4);

    dim3 gq(T_TOK / 128, D_DIM / 128);
    qproj_mma_kernel<<<gq, 256>>>(bq);

    band_kernel<<<T_TOK / TI, 256>>>(emb);

    const int blocks = (n_spans * 32 + 255) / 256;
    span_out_kernel<<<blocks, 256>>>(emb, spans, out, n_spans);
}